// round 6
// baseline (speedup 1.0000x reference)
#include <cuda_runtime.h>
#include <cuda_bf16.h>
#include <math.h>

// ---------------------------------------------------------------------------
// Problem constants
// ---------------------------------------------------------------------------
#define BATCH   2
#define SEQ     2048
#define EMBED   1024
#define HEADS   16
#define HDIM    64
#define HIDDEN  4096
#define MTOT    (BATCH * SEQ)          // 4096 rows
#define LN_EPS  1e-5f

// ---------------------------------------------------------------------------
// Scratch (device globals — allocation-free rule)
// ---------------------------------------------------------------------------
__device__ float g_q   [MTOT * EMBED];
__device__ float g_k   [MTOT * EMBED];
__device__ float g_v   [MTOT * EMBED];
__device__ float g_ao  [MTOT * EMBED];   // attn @ V  (B,S,D)
__device__ float g_tmp [MTOT * EMBED];   // Wo output
__device__ float g_h   [MTOT * EMBED];   // post-LN1
__device__ float g_hid [MTOT * HIDDEN];  // gelu(h@W1+b1)
__device__ float g_mlp [MTOT * EMBED];   // W2 output

// ---------------------------------------------------------------------------
// Generic batched SGEMM: C = act(alpha * A @ B(^T) + bias)
//   A: [M,K] row-major, lda
//   B: TRANSB ? [N,K] : [K,N], ldb
//   C: [M,N] row-major, ldc
// Batch offset for grid z: b = z / Hn, h = z % Hn;  ptr += b*s?b + h*s?h
// Requirements: M % 128 == 0, K % 16 == 0 (holds for every call here).
// N handled with guards (attn@V has N=64).
// ---------------------------------------------------------------------------
#define BM 128
#define BN 128
#define BK 16

__device__ __forceinline__ float gelu_exact(float x) {
    return 0.5f * x * (1.0f + erff(x * 0.70710678118654752f));
}

template <bool TRANSB>
__global__ void __launch_bounds__(256)
sgemm_kernel(int M, int N, int K,
             const float* __restrict__ A, int lda,
             const float* __restrict__ B, int ldb,
             float*       __restrict__ C, int ldc,
             const float* __restrict__ bias,
             float alpha, int act,
             long long sAb, long long sAh,
             long long sBb, long long sBh,
             long long sCb, long long sCh, int Hn)
{
    __shared__ float As[BK][BM];
    __shared__ float Bs[BK][BN];

    const int z  = blockIdx.z;
    const int bb = z / Hn;
    const int hh = z % Hn;
    A += (long long)bb * sAb + (long long)hh * sAh;
    B += (long long)bb * sBb + (long long)hh * sBh;
    C += (long long)bb * sCb + (long long)hh * sCh;

    const int bm  = blockIdx.y * BM;
    const int bn  = blockIdx.x * BN;
    const int tid = threadIdx.x;
    const int tr  = tid >> 4;        // 0..15
    const int tc  = tid & 15;        // 0..15

    // load mapping (128 rows x 16 cols tile = 512 float4, 2 per thread)
    const int aRow0 = tid >> 2;        // 0..63
    const int aCol4 = (tid & 3) * 4;   // 0,4,8,12
    // non-trans B tile (16 x 128) mapping
    const int bRowK = tid >> 5;        // 0..7
    const int bCol4 = (tid & 31) * 4;  // 0..124

    float acc[8][8];
#pragma unroll
    for (int i = 0; i < 8; i++)
#pragma unroll
        for (int j = 0; j < 8; j++) acc[i][j] = 0.f;

    for (int k0 = 0; k0 < K; k0 += BK) {
        // ---- load A tile (always in-bounds: M%128==0, K%16==0) ----
#pragma unroll
        for (int rr = 0; rr < 2; rr++) {
            int row = aRow0 + rr * 64;
            float4 a = *(const float4*)(A + (long long)(bm + row) * lda + k0 + aCol4);
            As[aCol4 + 0][row] = a.x;
            As[aCol4 + 1][row] = a.y;
            As[aCol4 + 2][row] = a.z;
            As[aCol4 + 3][row] = a.w;
        }
        // ---- load B tile ----
        if (TRANSB) {
#pragma unroll
            for (int rr = 0; rr < 2; rr++) {
                int nrow = aRow0 + rr * 64;
                float4 b = make_float4(0.f, 0.f, 0.f, 0.f);
                if (bn + nrow < N)
                    b = *(const float4*)(B + (long long)(bn + nrow) * ldb + k0 + aCol4);
                Bs[aCol4 + 0][nrow] = b.x;
                Bs[aCol4 + 1][nrow] = b.y;
                Bs[aCol4 + 2][nrow] = b.z;
                Bs[aCol4 + 3][nrow] = b.w;
            }
        } else {
#pragma unroll
            for (int rr = 0; rr < 2; rr++) {
                int krow = bRowK + rr * 8;
                const float* src = B + (long long)(k0 + krow) * ldb + bn + bCol4;
                if (bn + bCol4 + 3 < N) {
                    *(float4*)&Bs[krow][bCol4] = *(const float4*)src;
                } else {
#pragma unroll
                    for (int e = 0; e < 4; e++)
                        Bs[krow][bCol4 + e] = (bn + bCol4 + e < N) ? src[e] : 0.f;
                }
            }
        }
        __syncthreads();

        // ---- compute ----
#pragma unroll
        for (int kk = 0; kk < BK; kk++) {
            float a[8], b[8];
            *(float4*)&a[0] = *(const float4*)&As[kk][tr * 4];
            *(float4*)&a[4] = *(const float4*)&As[kk][64 + tr * 4];
            *(float4*)&b[0] = *(const float4*)&Bs[kk][tc * 4];
            *(float4*)&b[4] = *(const float4*)&Bs[kk][64 + tc * 4];
#pragma unroll
            for (int i = 0; i < 8; i++)
#pragma unroll
                for (int j = 0; j < 8; j++)
                    acc[i][j] = fmaf(a[i], b[j], acc[i][j]);
        }
        __syncthreads();
    }

    // ---- epilogue ----
#pragma unroll
    for (int i = 0; i < 8; i++) {
        int row = bm + ((i < 4) ? (tr * 4 + i) : (64 + tr * 4 + i - 4));
#pragma unroll
        for (int j = 0; j < 8; j++) {
            int col = bn + ((j < 4) ? (tc * 4 + j) : (64 + tc * 4 + j - 4));
            if (col < N) {
                float v = acc[i][j] * alpha;
                if (bias) v += bias[col];
                if (act == 1) v = gelu_exact(v);
                C[(long long)row * ldc + col] = v;
            }
        }
    }
}

// ---------------------------------------------------------------------------
// Row softmax, in-place, rows of length SEQ=2048, one block (256 thr) per row
// ---------------------------------------------------------------------------
__global__ void __launch_bounds__(256)
softmax_kernel(float* __restrict__ attn)
{
    const int S = SEQ;
    float* p = attn + (long long)blockIdx.x * S;
    const int tid  = threadIdx.x;
    const int lane = tid & 31;
    const int wid  = tid >> 5;

    float v[8];
    float mx = -1e30f;
#pragma unroll
    for (int i = 0; i < 8; i++) {
        v[i] = p[i * 256 + tid];
        mx = fmaxf(mx, v[i]);
    }
#pragma unroll
    for (int o = 16; o; o >>= 1) mx = fmaxf(mx, __shfl_xor_sync(0xffffffffu, mx, o));

    __shared__ float red[8];
    if (lane == 0) red[wid] = mx;
    __syncthreads();
    float m = red[0];
#pragma unroll
    for (int i = 1; i < 8; i++) m = fmaxf(m, red[i]);

    float sum = 0.f;
#pragma unroll
    for (int i = 0; i < 8; i++) {
        v[i] = __expf(v[i] - m);
        sum += v[i];
    }
#pragma unroll
    for (int o = 16; o; o >>= 1) sum += __shfl_xor_sync(0xffffffffu, sum, o);
    __syncthreads();
    if (lane == 0) red[wid] = sum;
    __syncthreads();
    float tot = 0.f;
#pragma unroll
    for (int i = 0; i < 8; i++) tot += red[i];
    float inv = 1.0f / tot;
#pragma unroll
    for (int i = 0; i < 8; i++) p[i * 256 + tid] = v[i] * inv;
}

// ---------------------------------------------------------------------------
// out = LayerNorm(a + b) * gamma + beta ; rows of EMBED=1024, 256 thr/row
// ---------------------------------------------------------------------------
__global__ void __launch_bounds__(256)
add_ln_kernel(const float* __restrict__ a, const float* __restrict__ b,
              const float* __restrict__ gamma, const float* __restrict__ beta,
              float* __restrict__ out)
{
    const int D = EMBED;
    const long long base = (long long)blockIdx.x * D;
    const int tid  = threadIdx.x;
    const int lane = tid & 31;
    const int wid  = tid >> 5;

    float v[4];
    float s1 = 0.f, s2 = 0.f;
#pragma unroll
    for (int i = 0; i < 4; i++) {
        int col = i * 256 + tid;
        float x = a[base + col] + b[base + col];
        v[i] = x;
        s1 += x;
        s2 += x * x;
    }
#pragma unroll
    for (int o = 16; o; o >>= 1) {
        s1 += __shfl_xor_sync(0xffffffffu, s1, o);
        s2 += __shfl_xor_sync(0xffffffffu, s2, o);
    }
    __shared__ float r1[8], r2[8];
    if (lane == 0) { r1[wid] = s1; r2[wid] = s2; }
    __syncthreads();
    float t1 = 0.f, t2 = 0.f;
#pragma unroll
    for (int i = 0; i < 8; i++) { t1 += r1[i]; t2 += r2[i]; }
    float mu  = t1 * (1.0f / D);
    float var = t2 * (1.0f / D) - mu * mu;
    float inv = rsqrtf(var + LN_EPS);
#pragma unroll
    for (int i = 0; i < 4; i++) {
        int col = i * 256 + tid;
        out[base + col] = (v[i] - mu) * inv * gamma[col] + beta[col];
    }
}

// ---------------------------------------------------------------------------
// Host launcher
// ---------------------------------------------------------------------------
extern "C" void kernel_launch(void* const* d_in, const int* in_sizes, int n_in,
                              void* d_out, int out_size)
{
    const float* x  = (const float*)d_in[0];
    const float* Wq = (const float*)d_in[1];
    const float* bq = (const float*)d_in[2];
    const float* Wk = (const float*)d_in[3];
    const float* bk = (const float*)d_in[4];
    const float* Wv = (const float*)d_in[5];
    const float* bv = (const float*)d_in[6];
    const float* Wo = (const float*)d_in[7];
    const float* bo = (const float*)d_in[8];
    const float* W1 = (const float*)d_in[9];
    const float* b1 = (const float*)d_in[10];
    const float* W2 = (const float*)d_in[11];
    const float* b2 = (const float*)d_in[12];
    const float* gamma = (const float*)d_in[13];
    const float* beta  = (const float*)d_in[14];

    float* out  = (float*)d_out;                       // [B,S,D]
    float* attn = out + (long long)MTOT * EMBED;       // [B,H,S,S]

    float *q, *k, *v, *ao, *tmp, *h, *hid, *mlp;
    cudaGetSymbolAddress((void**)&q,   g_q);
    cudaGetSymbolAddress((void**)&k,   g_k);
    cudaGetSymbolAddress((void**)&v,   g_v);
    cudaGetSymbolAddress((void**)&ao,  g_ao);
    cudaGetSymbolAddress((void**)&tmp, g_tmp);
    cudaGetSymbolAddress((void**)&h,   g_h);
    cudaGetSymbolAddress((void**)&hid, g_hid);
    cudaGetSymbolAddress((void**)&mlp, g_mlp);

    const dim3 blk(256);
    const long long SD  = (long long)SEQ * EMBED;       // batch stride of x/q/k/v
    const long long SS  = (long long)SEQ * SEQ;         // per-head attn stride

    // --- QKV projections ---
    sgemm_kernel<false><<<dim3(EMBED / BN, MTOT / BM, 1), blk>>>(
        MTOT, EMBED, EMBED, x, EMBED, Wq, EMBED, q, EMBED, bq, 1.f, 0,
        0, 0, 0, 0, 0, 0, 1);
    sgemm_kernel<false><<<dim3(EMBED / BN, MTOT / BM, 1), blk>>>(
        MTOT, EMBED, EMBED, x, EMBED, Wk, EMBED, k, EMBED, bk, 1.f, 0,
        0, 0, 0, 0, 0, 0, 1);
    sgemm_kernel<false><<<dim3(EMBED / BN, MTOT / BM, 1), blk>>>(
        MTOT, EMBED, EMBED, x, EMBED, Wv, EMBED, v, EMBED, bv, 1.f, 0,
        0, 0, 0, 0, 0, 0, 1);

    // --- energy = (Q @ K^T) / sqrt(d)  -> written straight into attn slice ---
    sgemm_kernel<true><<<dim3(SEQ / BN, SEQ / BM, BATCH * HEADS), blk>>>(
        SEQ, SEQ, HDIM, q, EMBED, k, EMBED, attn, SEQ, nullptr, 0.125f, 0,
        SD, HDIM, SD, HDIM, (long long)HEADS * SS, SS, HEADS);

    // --- softmax rows (in place) ---
    softmax_kernel<<<BATCH * HEADS * SEQ, 256>>>(attn);

    // --- attn @ V ---
    sgemm_kernel<false><<<dim3(1, SEQ / BM, BATCH * HEADS), blk>>>(
        SEQ, HDIM, SEQ, attn, SEQ, v, EMBED, ao, EMBED, nullptr, 1.f, 0,
        (long long)HEADS * SS, SS, SD, HDIM, SD, HDIM, HEADS);

    // --- output projection ---
    sgemm_kernel<false><<<dim3(EMBED / BN, MTOT / BM, 1), blk>>>(
        MTOT, EMBED, EMBED, ao, EMBED, Wo, EMBED, tmp, EMBED, bo, 1.f, 0,
        0, 0, 0, 0, 0, 0, 1);

    // --- h = LN(x + attn_proj) ---
    add_ln_kernel<<<MTOT, 256>>>(x, tmp, gamma, beta, h);

    // --- MLP: gelu(h @ W1 + b1) ---
    sgemm_kernel<false><<<dim3(HIDDEN / BN, MTOT / BM, 1), blk>>>(
        MTOT, HIDDEN, EMBED, h, EMBED, W1, HIDDEN, hid, HIDDEN, b1, 1.f, 1,
        0, 0, 0, 0, 0, 0, 1);

    // --- mlp = hid @ W2 + b2 ---
    sgemm_kernel<false><<<dim3(EMBED / BN, MTOT / BM, 1), blk>>>(
        MTOT, EMBED, HIDDEN, hid, HIDDEN, W2, EMBED, mlp, EMBED, b2, 1.f, 0,
        0, 0, 0, 0, 0, 0, 1);

    // --- out = LN(mlp + h) ---
    add_ln_kernel<<<MTOT, 256>>>(mlp, h, gamma, beta, out);
}

// round 8
// speedup vs baseline: 2.6911x; 2.6911x over previous
#include <cuda_runtime.h>
#include <cuda_bf16.h>
#include <math.h>
#include <stdint.h>

#define BATCH   2
#define SEQ     2048
#define EMBED   1024
#define HEADS   16
#define HDIM    64
#define HIDDEN  4096
#define MTOT    (BATCH * SEQ)
#define LN_EPS  1e-5f

// ------------------------- scratch (device globals) -------------------------
__device__ float g_q  [MTOT * EMBED];
__device__ float g_k  [MTOT * EMBED];
__device__ float g_v  [MTOT * EMBED];
__device__ float g_ao [MTOT * EMBED];
__device__ float g_t1 [MTOT * EMBED];
__device__ float g_h  [MTOT * EMBED];
__device__ float g_hid[(size_t)MTOT * HIDDEN];
__device__ float g_mlp[MTOT * EMBED];

__device__ __nv_bfloat16 g_wq_h[EMBED*EMBED], g_wq_l[EMBED*EMBED];
__device__ __nv_bfloat16 g_wk_h[EMBED*EMBED], g_wk_l[EMBED*EMBED];
__device__ __nv_bfloat16 g_wv_h[EMBED*EMBED], g_wv_l[EMBED*EMBED];
__device__ __nv_bfloat16 g_wo_h[EMBED*EMBED], g_wo_l[EMBED*EMBED];
__device__ __nv_bfloat16 g_w1_h[(size_t)EMBED*HIDDEN], g_w1_l[(size_t)EMBED*HIDDEN];
__device__ __nv_bfloat16 g_w2_h[(size_t)EMBED*HIDDEN], g_w2_l[(size_t)EMBED*HIDDEN];
__device__ __nv_bfloat16 g_vT_h[(size_t)BATCH*EMBED*SEQ], g_vT_l[(size_t)BATCH*EMBED*SEQ];

// ------------------------------- helpers ------------------------------------
__device__ __forceinline__ uint32_t smem_u32(const void* p) {
    uint32_t a;
    asm("{ .reg .u64 t; cvta.to.shared.u64 t, %1; cvt.u32.u64 %0, t; }" : "=r"(a) : "l"(p));
    return a;
}
// blocked-atom (8 rows x 128B) + SW128 swizzle; rows hold 64 bf16 (one K-chunk)
__device__ __forceinline__ uint32_t sw_off(int row, int kb) {
    uint32_t o = ((uint32_t)(row >> 3) << 10) + ((uint32_t)(row & 7) << 7) + (uint32_t)kb;
    return o ^ ((o >> 3) & 0x70);
}
__device__ __forceinline__ uint32_t b2u(__nv_bfloat162 h) { return *(uint32_t*)&h; }

__device__ __forceinline__ void ldm_x4(uint32_t* r, uint32_t a) {
    asm volatile("ldmatrix.sync.aligned.m8n8.x4.shared.b16 {%0,%1,%2,%3}, [%4];"
                 : "=r"(r[0]), "=r"(r[1]), "=r"(r[2]), "=r"(r[3]) : "r"(a));
}
__device__ __forceinline__ void ldm_x2(uint32_t* r, uint32_t a) {
    asm volatile("ldmatrix.sync.aligned.m8n8.x2.shared.b16 {%0,%1}, [%2];"
                 : "=r"(r[0]), "=r"(r[1]) : "r"(a));
}
__device__ __forceinline__ void mma_bf16(float* c, const uint32_t* a, const uint32_t* b) {
    asm volatile("mma.sync.aligned.m16n8k16.row.col.f32.bf16.bf16.f32 "
                 "{%0,%1,%2,%3}, {%4,%5,%6,%7}, {%8,%9}, {%0,%1,%2,%3};"
                 : "+f"(c[0]), "+f"(c[1]), "+f"(c[2]), "+f"(c[3])
                 : "r"(a[0]), "r"(a[1]), "r"(a[2]), "r"(a[3]), "r"(b[0]), "r"(b[1]));
}
__device__ __forceinline__ void cp_async16(uint32_t dst, const void* src) {
    asm volatile("cp.async.ca.shared.global [%0], [%1], 16;" :: "r"(dst), "l"(src) : "memory");
}
#define CP_COMMIT() asm volatile("cp.async.commit_group;" ::: "memory")
#define CP_WAIT0()  asm volatile("cp.async.wait_group 0;" ::: "memory")

__device__ __forceinline__ float gelu_exact(float x) {
    return 0.5f * x * (1.0f + erff(x * 0.70710678118654752f));
}

// direct fp32 -> bf16 hi/lo staging (used for B when fp32; prologue A)
__device__ __forceinline__ void stage_f32(const float* __restrict__ src, int ld,
                                          int k0, char* dst, int rows, int gs, int tid) {
    int iters = (rows * 16) >> 8;
    for (int it = 0; it < iters; it++) {
        int id = it * 256 + tid;
        int row = id >> 4, c4 = (id & 15) << 2;
        float4 v = *(const float4*)(src + (size_t)row * ld + k0 + c4);
        __nv_bfloat162 h01 = __floats2bfloat162_rn(v.x, v.y);
        __nv_bfloat162 h23 = __floats2bfloat162_rn(v.z, v.w);
        float2 f01 = __bfloat1622float2(h01);
        float2 f23 = __bfloat1622float2(h23);
        __nv_bfloat162 l01 = __floats2bfloat162_rn(v.x - f01.x, v.y - f01.y);
        __nv_bfloat162 l23 = __floats2bfloat162_rn(v.z - f23.x, v.w - f23.y);
        uint32_t off = sw_off(row, c4 * 2);
        *(uint2*)(dst + off)      = make_uint2(b2u(h01), b2u(h23));
        *(uint2*)(dst + gs + off) = make_uint2(b2u(l01), b2u(l23));
    }
}

// ---------------------------------------------------------------------------
// Warp-tiled bf16x3 mma.sync GEMM:  C = act(alpha * A@B^T + bias)
//   A: [M,K] fp32 (row-major)        — activations, split on the fly
//   B: [N,K] fp32 OR presplit bf16   — weights presplit, K-major
// grid: (N/NT, M/128, nz) ; z decodes (batch, head) via Hn and strides.
// ---------------------------------------------------------------------------
template <int NT>
__global__ void __launch_bounds__(256, 1)
gemm_mma(int K,
         const float* __restrict__ A, int lda,
         const float* __restrict__ Bf,
         const __nv_bfloat16* __restrict__ Bh,
         const __nv_bfloat16* __restrict__ Bl, int ldb,
         float* __restrict__ C, int ldc,
         const float* __restrict__ bias, float alpha, int act,
         long long sAb, long long sAh, long long sBb, long long sBh,
         long long sCb, long long sCh, int Hn)
{
    constexpr int AG  = 16384;        // A hi/lo group bytes (128 rows x 128B)
    constexpr int BG  = NT * 128;     // B group bytes
    constexpr int ASZ = 2 * AG, BSZ = 2 * BG, BUF = ASZ + BSZ;
    constexpr int WGN = (NT == 128) ? 4 : 2;       // warps along N
    constexpr int WM  = (NT == 128) ? 64 : 32;     // warp tile M
    constexpr int MF  = WM / 16;                   // m-frags (4 or 2)
    constexpr int NF  = 4;                         // n-frags (32/8)

    extern __shared__ char smem[];
    const uint32_t sm32 = smem_u32(smem);
    const int tid = threadIdx.x, wid = tid >> 5, lane = tid & 31;
    const int warp_m = wid / WGN, warp_n = wid % WGN;
    const int wm0 = warp_m * WM, wn0 = warp_n * 32;

    const int bn = blockIdx.x * NT, bm = blockIdx.y * 128;
    const int bb = blockIdx.z / Hn, hh = blockIdx.z % Hn;
    A  += (long long)bb * sAb + (long long)hh * sAh + (long long)bm * lda;
    if (Bf) Bf += (long long)bb * sBb + (long long)hh * sBh + (long long)bn * ldb;
    if (Bh) { long long o = (long long)bb * sBb + (long long)hh * sBh + (long long)bn * ldb;
              Bh += o; Bl += o; }
    C  += (long long)bb * sCb + (long long)hh * sCh;

    const int NC = K >> 6;

    // per-lane ldmatrix address components
    const int a_r = lane & 15, a_k16 = (lane >> 4) << 4;       // x4
    const int b_r = lane & 7,  b_k16 = ((lane >> 3) & 1) << 4; // x2

    float acc[MF][NF][4];
#pragma unroll
    for (int mi = 0; mi < MF; mi++)
#pragma unroll
        for (int ni = 0; ni < NF; ni++)
#pragma unroll
            for (int e = 0; e < 4; e++) acc[mi][ni][e] = 0.f;

    // ---- prologue: stage chunk 0 ----
    stage_f32(A, lda, 0, smem, 128, AG, tid);
    if (Bf) {
        stage_f32(Bf, ldb, 0, smem + ASZ, NT, BG, tid);
    } else {
#pragma unroll
        for (int g = 0; g < 2; g++) {
            const __nv_bfloat16* src = g ? Bl : Bh;
            for (int it = 0; it < NT / 32; it++) {
                int id = it * 256 + tid;
                int row = id >> 3, u = id & 7;
                cp_async16(sm32 + ASZ + g * BG + sw_off(row, u * 16),
                           src + (size_t)row * ldb + u * 8);
            }
        }
        CP_COMMIT(); CP_WAIT0();
    }
    __syncthreads();

    float4 pf[8];
    for (int c = 0; c < NC; c++) {
        const int buf = c & 1;
        const uint32_t sA = sm32 + buf * BUF;
        const uint32_t sB = sA + ASZ;
        char* nxt = smem + (buf ^ 1) * BUF;
        const bool more = (c + 1 < NC);

        // issue next chunk's loads (A -> regs, B -> cp.async) before MMA
        if (more) {
            const int k0 = (c + 1) << 6;
#pragma unroll
            for (int i = 0; i < 8; i++) {
                int id = i * 256 + tid;
                int row = id >> 4, c4 = (id & 15) << 2;
                pf[i] = *(const float4*)(A + (size_t)row * lda + k0 + c4);
            }
            if (!Bf) {
#pragma unroll
                for (int g = 0; g < 2; g++) {
                    const __nv_bfloat16* src = g ? Bl : Bh;
                    for (int it = 0; it < NT / 32; it++) {
                        int id = it * 256 + tid;
                        int row = id >> 3, u = id & 7;
                        cp_async16(smem_u32(nxt) + ASZ + g * BG + sw_off(row, u * 16),
                                   src + (size_t)row * ldb + k0 + u * 8);
                    }
                }
                CP_COMMIT();
            }
        }

        // ---- MMA over this chunk (4 k-steps of 16) ----
#pragma unroll
        for (int ks = 0; ks < 4; ks++) {
            uint32_t ah[MF][4], al[MF][4], bh[NF][2], bl[NF][2];
#pragma unroll
            for (int mi = 0; mi < MF; mi++) {
                uint32_t off = sw_off(wm0 + mi * 16 + a_r, ks * 32 + a_k16);
                ldm_x4(ah[mi], sA + off);
                ldm_x4(al[mi], sA + AG + off);
            }
#pragma unroll
            for (int ni = 0; ni < NF; ni++) {
                uint32_t off = sw_off(wn0 + ni * 8 + b_r, ks * 32 + b_k16);
                ldm_x2(bh[ni], sB + off);
                ldm_x2(bl[ni], sB + BG + off);
            }
#pragma unroll
            for (int mi = 0; mi < MF; mi++)
#pragma unroll
                for (int ni = 0; ni < NF; ni++) {
                    mma_bf16(acc[mi][ni], ah[mi], bh[ni]);
                    mma_bf16(acc[mi][ni], ah[mi], bl[ni]);
                    mma_bf16(acc[mi][ni], al[mi], bh[ni]);
                }
        }

        // ---- store prefetched A (data arrived during MMA) ----
        if (more) {
#pragma unroll
            for (int i = 0; i < 8; i++) {
                int id = i * 256 + tid;
                int row = id >> 4, c4 = (id & 15) << 2;
                float4 v = pf[i];
                __nv_bfloat162 h01 = __floats2bfloat162_rn(v.x, v.y);
                __nv_bfloat162 h23 = __floats2bfloat162_rn(v.z, v.w);
                float2 f01 = __bfloat1622float2(h01);
                float2 f23 = __bfloat1622float2(h23);
                __nv_bfloat162 l01 = __floats2bfloat162_rn(v.x - f01.x, v.y - f01.y);
                __nv_bfloat162 l23 = __floats2bfloat162_rn(v.z - f23.x, v.w - f23.y);
                uint32_t off = sw_off(row, c4 * 2);
                *(uint2*)(nxt + off)      = make_uint2(b2u(h01), b2u(h23));
                *(uint2*)(nxt + AG + off) = make_uint2(b2u(l01), b2u(l23));
            }
            if (Bf) stage_f32(Bf, ldb, (c + 1) << 6, nxt + ASZ, NT, BG, tid);
            else    CP_WAIT0();
        }
        __syncthreads();
    }

    // ---- epilogue: regs -> gmem, fused alpha/bias/gelu ----
#pragma unroll
    for (int mi = 0; mi < MF; mi++) {
        const int r0 = bm + wm0 + mi * 16 + (lane >> 2);
#pragma unroll
        for (int ni = 0; ni < NF; ni++) {
            const int cb = bn + wn0 + ni * 8 + (lane & 3) * 2;
            float b0 = bias ? bias[cb] : 0.f, b1 = bias ? bias[cb + 1] : 0.f;
            float v0 = acc[mi][ni][0] * alpha + b0;
            float v1 = acc[mi][ni][1] * alpha + b1;
            float v2 = acc[mi][ni][2] * alpha + b0;
            float v3 = acc[mi][ni][3] * alpha + b1;
            if (act) { v0 = gelu_exact(v0); v1 = gelu_exact(v1);
                       v2 = gelu_exact(v2); v3 = gelu_exact(v3); }
            *(float2*)(C + (size_t)r0 * ldc + cb)       = make_float2(v0, v1);
            *(float2*)(C + (size_t)(r0 + 8) * ldc + cb) = make_float2(v2, v3);
        }
    }
}

// -------- transpose + split:  in [K][N] fp32  ->  out [N][K] bf16 hi/lo -----
__global__ void __launch_bounds__(256)
transpose_split(const float* __restrict__ in, int K, int N,
                __nv_bfloat16* __restrict__ oh, __nv_bfloat16* __restrict__ ol)
{
    __shared__ float tb[32][33];
    const int n0 = blockIdx.x * 32, k0 = blockIdx.y * 32;
    const int tx = threadIdx.x & 31, ty = threadIdx.x >> 5;
    for (int j = ty; j < 32; j += 8)
        tb[j][tx] = in[(size_t)(k0 + j) * N + n0 + tx];
    __syncthreads();
    for (int j = ty; j < 32; j += 8) {
        float v = tb[tx][j];
        __nv_bfloat16 h = __float2bfloat16(v);
        __nv_bfloat16 l = __float2bfloat16(v - __bfloat162float(h));
        size_t o = (size_t)(n0 + j) * K + k0 + tx;
        oh[o] = h; ol[o] = l;
    }
}

// ------------------------------- softmax ------------------------------------
__global__ void __launch_bounds__(256)
softmax_kernel(float* __restrict__ attn)
{
    float* p = attn + (long long)blockIdx.x * SEQ;
    const int tid = threadIdx.x, lane = tid & 31, wid = tid >> 5;
    float v[8], mx = -1e30f;
#pragma unroll
    for (int i = 0; i < 8; i++) { v[i] = p[i * 256 + tid]; mx = fmaxf(mx, v[i]); }
#pragma unroll
    for (int o = 16; o; o >>= 1) mx = fmaxf(mx, __shfl_xor_sync(0xffffffffu, mx, o));
    __shared__ float red[8];
    if (lane == 0) red[wid] = mx;
    __syncthreads();
    float m = red[0];
#pragma unroll
    for (int i = 1; i < 8; i++) m = fmaxf(m, red[i]);
    float sum = 0.f;
#pragma unroll
    for (int i = 0; i < 8; i++) { v[i] = __expf(v[i] - m); sum += v[i]; }
#pragma unroll
    for (int o = 16; o; o >>= 1) sum += __shfl_xor_sync(0xffffffffu, sum, o);
    __syncthreads();
    if (lane == 0) red[wid] = sum;
    __syncthreads();
    float tot = 0.f;
#pragma unroll
    for (int i = 0; i < 8; i++) tot += red[i];
    float inv = 1.0f / tot;
#pragma unroll
    for (int i = 0; i < 8; i++) p[i * 256 + tid] = v[i] * inv;
}

// ------------------------------ add + LN ------------------------------------
__global__ void __launch_bounds__(256)
add_ln_kernel(const float* __restrict__ a, const float* __restrict__ b,
              const float* __restrict__ gamma, const float* __restrict__ beta,
              float* __restrict__ out)
{
    const long long base = (long long)blockIdx.x * EMBED;
    const int tid = threadIdx.x, lane = tid & 31, wid = tid >> 5;
    float v[4], s1 = 0.f, s2 = 0.f;
#pragma unroll
    for (int i = 0; i < 4; i++) {
        int col = i * 256 + tid;
        float x = a[base + col] + b[base + col];
        v[i] = x; s1 += x; s2 += x * x;
    }
#pragma unroll
    for (int o = 16; o; o >>= 1) {
        s1 += __shfl_xor_sync(0xffffffffu, s1, o);
        s2 += __shfl_xor_sync(0xffffffffu, s2, o);
    }
    __shared__ float r1[8], r2[8];
    if (lane == 0) { r1[wid] = s1; r2[wid] = s2; }
    __syncthreads();
    float t1 = 0.f, t2 = 0.f;
#pragma unroll
    for (int i = 0; i < 8; i++) { t1 += r1[i]; t2 += r2[i]; }
    float mu = t1 * (1.0f / EMBED);
    float var = t2 * (1.0f / EMBED) - mu * mu;
    float inv = rsqrtf(var + LN_EPS);
#pragma unroll
    for (int i = 0; i < 4; i++) {
        int col = i * 256 + tid;
        out[base + col] = (v[i] - mu) * inv * gamma[col] + beta[col];
    }
}

// ------------------------------- launcher -----------------------------------
extern "C" void kernel_launch(void* const* d_in, const int* in_sizes, int n_in,
                              void* d_out, int out_size)
{
    const float* x  = (const float*)d_in[0];
    const float* Wq = (const float*)d_in[1];  const float* bq = (const float*)d_in[2];
    const float* Wk = (const float*)d_in[3];  const float* bk = (const float*)d_in[4];
    const float* Wv = (const float*)d_in[5];  const float* bv = (const float*)d_in[6];
    const float* Wo = (const float*)d_in[7];  const float* bo = (const float*)d_in[8];
    const float* W1 = (const float*)d_in[9];  const float* b1 = (const float*)d_in[10];
    const float* W2 = (const float*)d_in[11]; const float* b2 = (const float*)d_in[12];
    const float* gamma = (const float*)d_in[13];
    const float* beta  = (const float*)d_in[14];

    float* out  = (float*)d_out;
    float* attn = out + (long long)MTOT * EMBED;

    float *q, *k, *v, *ao, *t1, *h, *hid, *mlp;
    cudaGetSymbolAddress((void**)&q,   g_q);
    cudaGetSymbolAddress((void**)&k,   g_k);
    cudaGetSymbolAddress((void**)&v,   g_v);
    cudaGetSymbolAddress((void**)&ao,  g_ao);
    cudaGetSymbolAddress((void**)&t1,  g_t1);
    cudaGetSymbolAddress((void**)&h,   g_h);
    cudaGetSymbolAddress((void**)&hid, g_hid);
    cudaGetSymbolAddress((void**)&mlp, g_mlp);

    __nv_bfloat16 *wqh,*wql,*wkh,*wkl,*wvh,*wvl,*woh,*wol,*w1h,*w1l,*w2h,*w2l,*vth,*vtl;
    cudaGetSymbolAddress((void**)&wqh, g_wq_h); cudaGetSymbolAddress((void**)&wql, g_wq_l);
    cudaGetSymbolAddress((void**)&wkh, g_wk_h); cudaGetSymbolAddress((void**)&wkl, g_wk_l);
    cudaGetSymbolAddress((void**)&wvh, g_wv_h); cudaGetSymbolAddress((void**)&wvl, g_wv_l);
    cudaGetSymbolAddress((void**)&woh, g_wo_h); cudaGetSymbolAddress((void**)&wol, g_wo_l);
    cudaGetSymbolAddress((void**)&w1h, g_w1_h); cudaGetSymbolAddress((void**)&w1l, g_w1_l);
    cudaGetSymbolAddress((void**)&w2h, g_w2_h); cudaGetSymbolAddress((void**)&w2l, g_w2_l);
    cudaGetSymbolAddress((void**)&vth, g_vT_h); cudaGetSymbolAddress((void**)&vtl, g_vT_l);

    const int SM128 = 2 * (32768 + 2 * 128 * 128);   // 131072
    const int SM64  = 2 * (32768 + 2 * 64  * 128);   // 98304
    cudaFuncSetAttribute(gemm_mma<128>, cudaFuncAttributeMaxDynamicSharedMemorySize, SM128);
    cudaFuncSetAttribute(gemm_mma<64>,  cudaFuncAttributeMaxDynamicSharedMemorySize, SM64);

    const long long SD = (long long)SEQ * EMBED;
    const long long SS = (long long)SEQ * SEQ;

    // weight prep: [K][N] -> [N][K] bf16 hi/lo
    transpose_split<<<dim3(EMBED/32,  EMBED/32), 256>>>(Wq, EMBED, EMBED, wqh, wql);
    transpose_split<<<dim3(EMBED/32,  EMBED/32), 256>>>(Wk, EMBED, EMBED, wkh, wkl);
    transpose_split<<<dim3(EMBED/32,  EMBED/32), 256>>>(Wv, EMBED, EMBED, wvh, wvl);
    transpose_split<<<dim3(EMBED/32,  EMBED/32), 256>>>(Wo, EMBED, EMBED, woh, wol);
    transpose_split<<<dim3(HIDDEN/32, EMBED/32), 256>>>(W1, EMBED, HIDDEN, w1h, w1l);
    transpose_split<<<dim3(EMBED/32,  HIDDEN/32),256>>>(W2, HIDDEN, EMBED, w2h, w2l);

    // QKV projections
    gemm_mma<128><<<dim3(EMBED/128, MTOT/128, 1), 256, SM128>>>(EMBED,
        x, EMBED, 0, wqh, wql, EMBED, q, EMBED, bq, 1.f, 0, 0,0,0,0,0,0, 1);
    gemm_mma<128><<<dim3(EMBED/128, MTOT/128, 1), 256, SM128>>>(EMBED,
        x, EMBED, 0, wkh, wkl, EMBED, k, EMBED, bk, 1.f, 0, 0,0,0,0,0,0, 1);
    gemm_mma<128><<<dim3(EMBED/128, MTOT/128, 1), 256, SM128>>>(EMBED,
        x, EMBED, 0, wvh, wvl, EMBED, v, EMBED, bv, 1.f, 0, 0,0,0,0,0,0, 1);

    // vT per batch: [S][D] -> [D][S] bf16 hi/lo
    transpose_split<<<dim3(EMBED/32, SEQ/32), 256>>>(v,      SEQ, EMBED, vth, vtl);
    transpose_split<<<dim3(EMBED/32, SEQ/32), 256>>>(v + SD, SEQ, EMBED,
        vth + (size_t)EMBED*SEQ, vtl + (size_t)EMBED*SEQ);

    // energy = (Q @ K^T) / 8  -> attn slice of d_out   (A,B both fp32; K=64)
    gemm_mma<128><<<dim3(SEQ/128, SEQ/128, BATCH*HEADS), 256, SM128>>>(HDIM,
        q, EMBED, k, 0, 0, EMBED, attn, SEQ, 0, 0.125f, 0,
        SD, HDIM, SD, HDIM, (long long)HEADS*SS, SS, HEADS);

    softmax_kernel<<<BATCH*HEADS*SEQ, 256>>>(attn);

    // attn @ V   (A=attn fp32, B=vT presplit; per-head N=64)
    gemm_mma<64><<<dim3(1, SEQ/128, BATCH*HEADS), 256, SM64>>>(SEQ,
        attn, SEQ, 0, vth, vtl, SEQ, ao, EMBED, 0, 1.f, 0,
        (long long)HEADS*SS, SS, (long long)EMBED*SEQ, (long long)HDIM*SEQ,
        SD, HDIM, HEADS);

    // output projection
    gemm_mma<128><<<dim3(EMBED/128, MTOT/128, 1), 256, SM128>>>(EMBED,
        ao, EMBED, 0, woh, wol, EMBED, t1, EMBED, bo, 1.f, 0, 0,0,0,0,0,0, 1);

    add_ln_kernel<<<MTOT, 256>>>(x, t1, gamma, beta, h);

    // MLP
    gemm_mma<128><<<dim3(HIDDEN/128, MTOT/128, 1), 256, SM128>>>(EMBED,
        h, EMBED, 0, w1h, w1l, EMBED, hid, HIDDEN, b1, 1.f, 1, 0,0,0,0,0,0, 1);
    gemm_mma<128><<<dim3(EMBED/128, MTOT/128, 1), 256, SM128>>>(HIDDEN,
        hid, HIDDEN, 0, w2h, w2l, HIDDEN, mlp, EMBED, b2, 1.f, 0, 0,0,0,0,0,0, 1);

    add_ln_kernel<<<MTOT, 256>>>(mlp, h, gamma, beta, out);
}